// round 8
// baseline (speedup 1.0000x reference)
#include <cuda_runtime.h>
#include <cuda_fp16.h>

#define NMAX   100000
#define EMAX   1600000
#define CIN_   128
#define COUT_  64
#define SCAN_C 1024
#define NBLK_MAX 128

// Scratch (device globals — no allocation allowed).
// Invariants at entry (restored each call; static zero-init on first call):
//   g_deg == 0, g_scan_cnt == 0.
__device__ __half2 g_H2[NMAX * (COUT_ / 2)];   // Hs = (X@W+b)*dinv, fp16
__device__ float   g_dinv[NMAX];
__device__ int     g_deg[NMAX];
__device__ int     g_rowoff[NMAX];             // block-local exclusive prefix
__device__ int     g_boff[NBLK_MAX];           // per-1024-chunk global offset
__device__ int     g_bsum[NBLK_MAX];
__device__ int     g_pos[EMAX];
__device__ int     g_edge[EMAX];               // src only, CSR by dst
__device__ int     g_scan_cnt;

// ---------------------------------------------------------------------------
// 1) degree count + slot record, 4 edges/thread
// ---------------------------------------------------------------------------
__global__ __launch_bounds__(256) void degpos_kernel(const int* __restrict__ dst, int E) {
    int base = (blockIdx.x * 256 + threadIdx.x) * 4;
    if (base + 3 < E) {
        int4 d = *(const int4*)(dst + base);
        int4 p;
        p.x = atomicAdd(&g_deg[d.x], 1);
        p.y = atomicAdd(&g_deg[d.y], 1);
        p.z = atomicAdd(&g_deg[d.z], 1);
        p.w = atomicAdd(&g_deg[d.w], 1);
        *(int4*)(g_pos + base) = p;
    } else {
        for (int i = base; i < E; i++)
            g_pos[i] = atomicAdd(&g_deg[dst[i]], 1);
    }
}

// ---------------------------------------------------------------------------
// 2) scan: block-local exclusive prefix of deg, dinv=rsqrt(1+deg), deg:=0;
//    last-finishing block scans the <=128 block sums into g_boff.
// ---------------------------------------------------------------------------
__global__ __launch_bounds__(256) void scan_kernel(int n) {
    __shared__ int wsum[8];
    __shared__ int is_last;
    const int b    = blockIdx.x;
    const int base = b * SCAN_C + threadIdx.x * 4;
    const int lane = threadIdx.x & 31;
    const int warp = threadIdx.x >> 5;

    int v[4];
    #pragma unroll
    for (int i = 0; i < 4; i++) {
        int idx = base + i;
        v[i] = (idx < n) ? g_deg[idx] : 0;
        if (idx < n) {
            g_dinv[idx] = rsqrtf(1.0f + (float)v[i]);
            g_deg[idx]  = 0;                    // restore invariant
        }
    }
    int tsum = v[0] + v[1] + v[2] + v[3];

    int x = tsum;
    #pragma unroll
    for (int off = 1; off < 32; off <<= 1) {
        int y = __shfl_up_sync(0xFFFFFFFFu, x, off);
        if (lane >= off) x += y;
    }
    if (lane == 31) wsum[warp] = x;
    __syncthreads();
    if (threadIdx.x == 0) {
        int run = 0;
        #pragma unroll
        for (int w = 0; w < 8; w++) { int t = wsum[w]; wsum[w] = run; run += t; }
        g_bsum[b] = run;
    }
    __syncthreads();

    int run = wsum[warp] + x - tsum;
    #pragma unroll
    for (int i = 0; i < 4; i++) {
        int idx = base + i;
        if (idx < n) g_rowoff[idx] = run;
        run += v[i];
    }

    if (threadIdx.x == 0) {
        __threadfence();
        int old = atomicAdd(&g_scan_cnt, 1);
        is_last = (old == (int)gridDim.x - 1);
    }
    __syncthreads();
    if (is_last) {
        __threadfence();
        __shared__ int sp[NBLK_MAX];
        const int t = threadIdx.x;
        const int nblk = gridDim.x;
        if (t < NBLK_MAX) sp[t] = (t < nblk) ? g_bsum[t] : 0;
        __syncthreads();
        #pragma unroll
        for (int s = 1; s < NBLK_MAX; s <<= 1) {
            int vv = 0;
            if (t < NBLK_MAX && t >= s) vv = sp[t - s];
            __syncthreads();
            if (t < NBLK_MAX) sp[t] += vv;
            __syncthreads();
        }
        if (t < nblk) g_boff[t] = (t == 0) ? 0 : sp[t - 1];
        if (t == 0) g_scan_cnt = 0;             // restore invariant
    }
}

// ---------------------------------------------------------------------------
// 3) GEMM: Hs = (X @ W + b) * dinv — packed fma.rn.f32x2, fp16 epilogue
// ---------------------------------------------------------------------------
#define FMA2(d, a, b) asm("fma.rn.f32x2 %0, %1, %2, %3;" \
                          : "=l"(d) : "l"(a), "l"(b), "l"(d))

__global__ __launch_bounds__(256) void gemm_kernel(
    const float* __restrict__ X, const float* __restrict__ W,
    const float* __restrict__ bias, int n)
{
    __shared__ float2 Xs2[16][130];
    __shared__ float  Ws[16][64];

    const int tid  = threadIdx.x;
    const int tcol = tid & 15;
    const int trow = tid >> 4;
    const int row0 = blockIdx.x * 128;

    unsigned long long acc[8][2];
    #pragma unroll
    for (int r = 0; r < 8; r++) { acc[r][0] = 0ull; acc[r][1] = 0ull; }

    for (int k0 = 0; k0 < CIN_; k0 += 16) {
        #pragma unroll
        for (int p = 0; p < 2; p++) {
            int r  = p * 64 + (tid >> 2);
            int kq = tid & 3;
            int rr = row0 + r;
            const float* xp = X + (long)(rr < n ? rr : 0) * CIN_ + k0 + kq * 4;
            float4 v = *(const float4*)xp;
            Xs2[kq * 4 + 0][r] = make_float2(v.x, v.x);
            Xs2[kq * 4 + 1][r] = make_float2(v.y, v.y);
            Xs2[kq * 4 + 2][r] = make_float2(v.z, v.z);
            Xs2[kq * 4 + 3][r] = make_float2(v.w, v.w);
        }
        {
            int k    = tid >> 4;
            int colq = tid & 15;
            float4 v = *(const float4*)(W + (long)(k0 + k) * COUT_ + colq * 4);
            *(float4*)&Ws[k][colq * 4] = v;
        }
        __syncthreads();

        #pragma unroll
        for (int kk = 0; kk < 16; kk++) {
            ulonglong2 a01 = *(const ulonglong2*)&Xs2[kk][trow * 8 + 0];
            ulonglong2 a23 = *(const ulonglong2*)&Xs2[kk][trow * 8 + 2];
            ulonglong2 a45 = *(const ulonglong2*)&Xs2[kk][trow * 8 + 4];
            ulonglong2 a67 = *(const ulonglong2*)&Xs2[kk][trow * 8 + 6];
            ulonglong2 b   = *(const ulonglong2*)&Ws[kk][tcol * 4];
            FMA2(acc[0][0], a01.x, b.x);  FMA2(acc[0][1], a01.x, b.y);
            FMA2(acc[1][0], a01.y, b.x);  FMA2(acc[1][1], a01.y, b.y);
            FMA2(acc[2][0], a23.x, b.x);  FMA2(acc[2][1], a23.x, b.y);
            FMA2(acc[3][0], a23.y, b.x);  FMA2(acc[3][1], a23.y, b.y);
            FMA2(acc[4][0], a45.x, b.x);  FMA2(acc[4][1], a45.x, b.y);
            FMA2(acc[5][0], a45.y, b.x);  FMA2(acc[5][1], a45.y, b.y);
            FMA2(acc[6][0], a67.x, b.x);  FMA2(acc[6][1], a67.x, b.y);
            FMA2(acc[7][0], a67.y, b.x);  FMA2(acc[7][1], a67.y, b.y);
        }
        __syncthreads();
    }

    float2 bb0 = *(const float2*)(bias + tcol * 4);
    float2 bb1 = *(const float2*)(bias + tcol * 4 + 2);
    #pragma unroll
    for (int r = 0; r < 8; r++) {
        int row = row0 + trow * 8 + r;
        if (row < n) {
            float di = g_dinv[row];
            float2 lo = *(const float2*)&acc[r][0];
            float2 hi = *(const float2*)&acc[r][1];
            __half2 h0 = __floats2half2_rn((lo.x + bb0.x) * di, (lo.y + bb0.y) * di);
            __half2 h1 = __floats2half2_rn((hi.x + bb1.x) * di, (hi.y + bb1.y) * di);
            g_H2[(long)row * 32 + tcol * 2]     = h0;
            g_H2[(long)row * 32 + tcol * 2 + 1] = h1;
        }
    }
}

// ---------------------------------------------------------------------------
// 4) CSR fill (atomic-free, src-only payload), 8 edges/thread for MLP
// ---------------------------------------------------------------------------
__global__ __launch_bounds__(256) void fill_kernel(
    const int* __restrict__ src, const int* __restrict__ dst, int E)
{
    int base = (blockIdx.x * 256 + threadIdx.x) * 8;
    if (base + 7 < E) {
        int4 s0 = *(const int4*)(src + base);
        int4 s1 = *(const int4*)(src + base + 4);
        int4 d0 = *(const int4*)(dst + base);
        int4 d1 = *(const int4*)(dst + base + 4);
        int4 p0 = *(const int4*)(g_pos + base);
        int4 p1 = *(const int4*)(g_pos + base + 4);
        int o0 = g_rowoff[d0.x] + g_boff[d0.x >> 10] + p0.x;
        int o1 = g_rowoff[d0.y] + g_boff[d0.y >> 10] + p0.y;
        int o2 = g_rowoff[d0.z] + g_boff[d0.z >> 10] + p0.z;
        int o3 = g_rowoff[d0.w] + g_boff[d0.w >> 10] + p0.w;
        int o4 = g_rowoff[d1.x] + g_boff[d1.x >> 10] + p1.x;
        int o5 = g_rowoff[d1.y] + g_boff[d1.y >> 10] + p1.y;
        int o6 = g_rowoff[d1.z] + g_boff[d1.z >> 10] + p1.z;
        int o7 = g_rowoff[d1.w] + g_boff[d1.w >> 10] + p1.w;
        g_edge[o0] = s0.x;  g_edge[o1] = s0.y;
        g_edge[o2] = s0.z;  g_edge[o3] = s0.w;
        g_edge[o4] = s1.x;  g_edge[o5] = s1.y;
        g_edge[o6] = s1.z;  g_edge[o7] = s1.w;
    } else {
        for (int i = base; i < E; i++) {
            int d = dst[i];
            g_edge[g_rowoff[d] + g_boff[d >> 10] + g_pos[i]] = src[i];
        }
    }
}

// ---------------------------------------------------------------------------
// 5) gather: one warp per node, one half2 per lane (64 cols), fp32 accum.
//    Edge indices prefetched 32-at-a-time via one coalesced load + shfl,
//    Hs loads unrolled x8 for MLP.
//    out[d] = relu( dinv[d] * ( Hs[d] + sum_e Hs[src] ) )
// ---------------------------------------------------------------------------
__device__ __forceinline__ float2 ldcs_h2f2(const __half2* p) {
    unsigned u;
    asm volatile("ld.global.cs.b32 %0, [%1];" : "=r"(u) : "l"(p));
    return __half22float2(*reinterpret_cast<__half2*>(&u));
}

__global__ __launch_bounds__(256) void gather_kernel(float* __restrict__ out,
                                                     int n, int E) {
    int node = (blockIdx.x * 256 + threadIdx.x) >> 5;
    if (node >= n) return;
    int lane = threadIdx.x & 31;

    float dd = g_dinv[node];
    int   r0 = g_rowoff[node] + g_boff[node >> 10];
    int   r1 = (node + 1 < n) ? (g_rowoff[node + 1] + g_boff[(node + 1) >> 10]) : E;
    int   m  = r1 - r0;

    float2 acc = __half22float2(g_H2[(long)node * 32 + lane]);

    const int* ep = &g_edge[r0];
    for (int j0 = 0; j0 < m; j0 += 32) {
        int cnt = min(m - j0, 32);
        int eidx = (lane < cnt) ? __ldg(ep + j0 + lane) : 0;

        int j = 0;
        for (; j + 8 <= cnt; j += 8) {
            int e0 = __shfl_sync(0xFFFFFFFFu, eidx, j + 0);
            int e1 = __shfl_sync(0xFFFFFFFFu, eidx, j + 1);
            int e2 = __shfl_sync(0xFFFFFFFFu, eidx, j + 2);
            int e3 = __shfl_sync(0xFFFFFFFFu, eidx, j + 3);
            int e4 = __shfl_sync(0xFFFFFFFFu, eidx, j + 4);
            int e5 = __shfl_sync(0xFFFFFFFFu, eidx, j + 5);
            int e6 = __shfl_sync(0xFFFFFFFFu, eidx, j + 6);
            int e7 = __shfl_sync(0xFFFFFFFFu, eidx, j + 7);
            float2 h0 = ldcs_h2f2(&g_H2[(long)e0 * 32 + lane]);
            float2 h1 = ldcs_h2f2(&g_H2[(long)e1 * 32 + lane]);
            float2 h2 = ldcs_h2f2(&g_H2[(long)e2 * 32 + lane]);
            float2 h3 = ldcs_h2f2(&g_H2[(long)e3 * 32 + lane]);
            float2 h4 = ldcs_h2f2(&g_H2[(long)e4 * 32 + lane]);
            float2 h5 = ldcs_h2f2(&g_H2[(long)e5 * 32 + lane]);
            float2 h6 = ldcs_h2f2(&g_H2[(long)e6 * 32 + lane]);
            float2 h7 = ldcs_h2f2(&g_H2[(long)e7 * 32 + lane]);
            acc.x += (h0.x + h1.x) + (h2.x + h3.x) + ((h4.x + h5.x) + (h6.x + h7.x));
            acc.y += (h0.y + h1.y) + (h2.y + h3.y) + ((h4.y + h5.y) + (h6.y + h7.y));
        }
        for (; j < cnt; j++) {
            int e = __shfl_sync(0xFFFFFFFFu, eidx, j);
            float2 hh = ldcs_h2f2(&g_H2[(long)e * 32 + lane]);
            acc.x += hh.x;  acc.y += hh.y;
        }
    }

    float2 o = make_float2(fmaxf(acc.x * dd, 0.0f), fmaxf(acc.y * dd, 0.0f));
    *(float2*)&out[(long)node * COUT_ + lane * 2] = o;
}

// ---------------------------------------------------------------------------
extern "C" void kernel_launch(void* const* d_in, const int* in_sizes, int n_in,
                              void* d_out, int out_size)
{
    const float* X    = (const float*)d_in[0];   // (N, 128)
    const float* W    = (const float*)d_in[1];   // (128, 64)
    const float* bias = (const float*)d_in[2];   // (64,)
    const int*   src  = (const int*)d_in[3];     // (E,)
    const int*   dst  = (const int*)d_in[4];     // (E,)
    float*       out  = (float*)d_out;           // (N, 64)

    const int n = in_sizes[0] / CIN_;
    const int E = in_sizes[3];
    const int nblk = (n + SCAN_C - 1) / SCAN_C;

    degpos_kernel<<<(E + 1023) / 1024, 256>>>(dst, E);
    scan_kernel<<<nblk, 256>>>(n);
    gemm_kernel<<<(n + 127) / 128, 256>>>(X, W, bias, n);
    fill_kernel<<<(E + 2047) / 2048, 256>>>(src, dst, E);
    gather_kernel<<<(int)(((long)n * 32 + 255) / 256), 256>>>(out, n, E);
}